// round 8
// baseline (speedup 1.0000x reference)
#include <cuda_runtime.h>
#include <cstdint>

// ResidualVQ eval forward — Round 7: 1-pass tf32 mma.sync approx GEMM
// + exact fp32 rescore within a provable margin (bit-identical to R1 argmin).

#define N_DIM 32
#define C_DIM 512
#define T_DIM 2048
#define K_CODES 512
#define Q_LAYERS 6
#define P_PTS (N_DIM * T_DIM)                 // 65536
#define QUANT_ELEMS (N_DIM * C_DIM * T_DIM)   // 33554432
#define IDX_ELEMS (P_PTS * Q_LAYERS)
#define MARGIN 4.0f

// -------- device scratch --------
__device__ float  g_resid[(size_t)P_PTS * C_DIM];   // [p][c]
__device__ float  g_adist[(size_t)P_PTS * K_CODES]; // approx distances, 128MB
__device__ float  g_rnorm[P_PTS];
__device__ float  g_minv[P_PTS];
__device__ float  g_cbnorm[Q_LAYERS * K_CODES];
__device__ unsigned long long g_pack[P_PTS];
__device__ int    g_idx[Q_LAYERS * P_PTS];
__device__ int    g_hist[K_CODES];
__device__ double g_commit_accum, g_loss_total, g_perp_total;

// -------- helpers --------
__device__ __forceinline__ uint4 tf32hi4(float4 v) {
    uint4 h;
    asm("cvt.rna.tf32.f32 %0, %1;" : "=r"(h.x) : "f"(v.x));
    asm("cvt.rna.tf32.f32 %0, %1;" : "=r"(h.y) : "f"(v.y));
    asm("cvt.rna.tf32.f32 %0, %1;" : "=r"(h.z) : "f"(v.z));
    asm("cvt.rna.tf32.f32 %0, %1;" : "=r"(h.w) : "f"(v.w));
    return h;
}
__device__ __forceinline__ void mma8(float* d, const uint32_t* a, const uint32_t* b) {
    asm volatile("mma.sync.aligned.m16n8k8.row.col.f32.tf32.tf32.f32 "
                 "{%0,%1,%2,%3}, {%4,%5,%6,%7}, {%8,%9}, {%0,%1,%2,%3};"
                 : "+f"(d[0]), "+f"(d[1]), "+f"(d[2]), "+f"(d[3])
                 : "r"(a[0]), "r"(a[1]), "r"(a[2]), "r"(a[3]), "r"(b[0]), "r"(b[1]));
}
__device__ __forceinline__ int swz(int row, int k) {
    return row * 32 + (k ^ ((row & 7) << 2));
}

// -------- small kernels --------
__global__ void init_kernel() {
    int t = threadIdx.x;
    if (t < K_CODES) g_hist[t] = 0;
    if (t == 0) { g_commit_accum = 0.0; g_loss_total = 0.0; g_perp_total = 0.0; }
}

// x[n][c][t] -> resid[n*T+t][c]
__global__ void transpose_in_kernel(const float* __restrict__ x) {
    __shared__ float tile[32][33];
    int tx = threadIdx.x, ty = threadIdx.y;
    int n = blockIdx.z, c0 = blockIdx.y * 32, t0 = blockIdx.x * 32;
#pragma unroll
    for (int i = 0; i < 4; i++) {
        int c = c0 + ty + i * 8;
        tile[ty + i * 8][tx] = x[((size_t)n * C_DIM + c) * T_DIM + t0 + tx];
    }
    __syncthreads();
#pragma unroll
    for (int i = 0; i < 4; i++) {
        int t = t0 + ty + i * 8;
        g_resid[((size_t)n * T_DIM + t) * C_DIM + c0 + tx] = tile[tx][ty + i * 8];
    }
}

// ||r||^2 per point (approx use only) + pack init
__global__ void prep_kernel() {
    int gw = (blockIdx.x * blockDim.x + threadIdx.x) >> 5;
    int lane = threadIdx.x & 31;
    if (gw >= P_PTS) return;
    const float4* rrow = (const float4*)(g_resid + (size_t)gw * C_DIM);
    float nsq = 0.f;
#pragma unroll
    for (int k = 0; k < 4; k++) {
        float4 r = rrow[lane + 32 * k];
        nsq = fmaf(r.x, r.x, fmaf(r.y, r.y, fmaf(r.z, r.z, fmaf(r.w, r.w, nsq))));
    }
#pragma unroll
    for (int o = 16; o; o >>= 1) nsq += __shfl_xor_sync(0xffffffffu, nsq, o);
    if (lane == 0) { g_rnorm[gw] = nsq; g_pack[gw] = ~0ull; }
}

__global__ void cbnorm_kernel(const float* __restrict__ cb) {
    int gw = (blockIdx.x * blockDim.x + threadIdx.x) >> 5;
    int lane = threadIdx.x & 31;
    if (gw >= Q_LAYERS * K_CODES) return;
    const float* row = cb + (size_t)gw * C_DIM;
    float s = 0.f;
    for (int c = lane; c < C_DIM; c += 32) { float v = row[c]; s = fmaf(v, v, s); }
#pragma unroll
    for (int o = 16; o; o >>= 1) s += __shfl_xor_sync(0xffffffffu, s, o);
    if (lane == 0) g_cbnorm[gw] = s;
}

// -------- phase A: tf32 approx distance GEMM --------
// Block: 128 points x 128 codes, 256 threads (8 warps = 4m x 2n).
// 1-pass hi-only tf32. Writes approx distances + packed approx-min atomicMin.
__global__ __launch_bounds__(256) void argmin_tc_kernel(const float* __restrict__ cb, int q) {
    extern __shared__ uint32_t ds[];
    __shared__ float sm_rn[128];
    __shared__ float sm_cbn[128];

    const int tid = threadIdx.x;
    const int lane = tid & 31;
    const int w = tid >> 5;
    const int wm = w & 3, wn = w >> 2;
    const int p0 = blockIdx.x * 128;
    const int n0 = blockIdx.y * 128;

    const float* __restrict__ Ag = g_resid + (size_t)p0 * C_DIM;
    const float* __restrict__ Bg = cb + ((size_t)q * K_CODES + n0) * C_DIM;

    if (tid < 128) {
        sm_rn[tid] = g_rnorm[p0 + tid];
        sm_cbn[tid] = g_cbnorm[q * K_CODES + n0 + tid];
    }

    int rowS[4], c0S[4];
#pragma unroll
    for (int i = 0; i < 4; i++) {
        int idx = tid + i * 256;
        rowS[i] = idx >> 3;
        c0S[i] = (idx & 7) << 2;
    }

    float acc[2][8][4];
#pragma unroll
    for (int mt = 0; mt < 2; mt++)
#pragma unroll
        for (int nt = 0; nt < 8; nt++)
#pragma unroll
            for (int j = 0; j < 4; j++) acc[mt][nt][j] = 0.f;

    float4 ra[4], rb[4];
#pragma unroll
    for (int i = 0; i < 4; i++) {
        ra[i] = *(const float4*)(Ag + (size_t)rowS[i] * C_DIM + c0S[i]);
        rb[i] = *(const float4*)(Bg + (size_t)rowS[i] * C_DIM + c0S[i]);
    }
    {
        uint32_t* Ah = ds, *Bh = ds + 4096;
#pragma unroll
        for (int i = 0; i < 4; i++) {
            int si = swz(rowS[i], c0S[i]);
            *(uint4*)&Ah[si] = tf32hi4(ra[i]);
            *(uint4*)&Bh[si] = tf32hi4(rb[i]);
        }
    }
    __syncthreads();

    for (int ci = 0; ci < 16; ci++) {
        const int buf = ci & 1;
        if (ci < 15) {
            const int k0 = (ci + 1) * 32;
#pragma unroll
            for (int i = 0; i < 4; i++) {
                ra[i] = *(const float4*)(Ag + (size_t)rowS[i] * C_DIM + k0 + c0S[i]);
                rb[i] = *(const float4*)(Bg + (size_t)rowS[i] * C_DIM + k0 + c0S[i]);
            }
        }

        const uint32_t* Ah = ds + buf * 8192;
        const uint32_t* Bh = Ah + 4096;

#pragma unroll
        for (int ks = 0; ks < 4; ks++) {
            const int k = ks * 8 + (lane & 3);
            uint32_t afh[2][4];
#pragma unroll
            for (int mt = 0; mt < 2; mt++) {
                int r0 = wm * 32 + mt * 16 + (lane >> 2);
                afh[mt][0] = Ah[swz(r0, k)];
                afh[mt][1] = Ah[swz(r0 + 8, k)];
                afh[mt][2] = Ah[swz(r0, k + 4)];
                afh[mt][3] = Ah[swz(r0 + 8, k + 4)];
            }
#pragma unroll
            for (int nt = 0; nt < 8; nt++) {
                int nr = wn * 64 + nt * 8 + (lane >> 2);
                uint32_t bh[2] = { Bh[swz(nr, k)], Bh[swz(nr, k + 4)] };
                mma8(acc[0][nt], afh[0], bh);
                mma8(acc[1][nt], afh[1], bh);
            }
        }

        if (ci < 15) {
            uint32_t* nAh = ds + (buf ^ 1) * 8192;
            uint32_t* nBh = nAh + 4096;
#pragma unroll
            for (int i = 0; i < 4; i++) {
                int si = swz(rowS[i], c0S[i]);
                *(uint4*)&nAh[si] = tf32hi4(ra[i]);
                *(uint4*)&nBh[si] = tf32hi4(rb[i]);
            }
        }
        __syncthreads();
    }

    // epilogue: approx dist = (rn - 2*dot) + cn; store adist; packed atomicMin
#pragma unroll
    for (int mt = 0; mt < 2; mt++) {
#pragma unroll
        for (int h = 0; h < 2; h++) {
            int rowl = wm * 32 + mt * 16 + h * 8 + (lane >> 2);
            float rn = sm_rn[rowl];
            float* adrow = g_adist + (size_t)(p0 + rowl) * K_CODES + n0;
            float bm = 3.4e38f; int bic = 0;
#pragma unroll
            for (int nt = 0; nt < 8; nt++) {
                int cl0 = wn * 64 + nt * 8 + 2 * (lane & 3);
                float v0 = __fadd_rn(__fsub_rn(rn, 2.0f * acc[mt][nt][h * 2 + 0]), sm_cbn[cl0]);
                float v1 = __fadd_rn(__fsub_rn(rn, 2.0f * acc[mt][nt][h * 2 + 1]), sm_cbn[cl0 + 1]);
                *(float2*)(adrow + cl0) = make_float2(v0, v1);
                if (v0 < bm) { bm = v0; bic = n0 + cl0; }
                if (v1 < bm) { bm = v1; bic = n0 + cl0 + 1; }
            }
            unsigned ub = __float_as_uint(bm);
            unsigned s = ub ^ ((unsigned)((int)ub >> 31) | 0x80000000u);
            atomicMin(&g_pack[p0 + rowl], ((unsigned long long)s << 32) | (unsigned)bic);
        }
    }
}

// -------- phase B: exact rescore within margin (bit-identical to R1) --------
__global__ __launch_bounds__(256) void rescore_kernel(const float* __restrict__ cb, int q) {
    __shared__ float rsm[8][512];
    const int w = threadIdx.x >> 5, lane = threadIdx.x & 31;
    const int p = blockIdx.x * 8 + w;

    // stage residual row
    const float4* rrow = (const float4*)(g_resid + (size_t)p * C_DIM);
    float4* rs4 = (float4*)rsm[w];
#pragma unroll
    for (int i = 0; i < 4; i++) rs4[lane + 32 * i] = rrow[lane + 32 * i];
    __syncwarp();
    const float* rs = rsm[w];

    // exact ||r||^2, sequential chain c=0..511 (matches R1's per-thread order)
    float rn = 0.f;
    for (int c = 0; c < C_DIM; c++) rn = fmaf(rs[c], rs[c], rn);

    // threshold from packed approx min
    unsigned long long key = g_pack[p];
    unsigned sb = (unsigned)(key >> 32);
    unsigned ub = (sb & 0x80000000u) ? (sb ^ 0x80000000u) : ~sb;
    float thr = __uint_as_float(ub) + MARGIN;

    const float* ad = g_adist + (size_t)p * K_CODES;
    const float* cbq = cb + (size_t)q * K_CODES * C_DIM;
    const float* cn = g_cbnorm + q * K_CODES;
    float bm = 3.4e38f; int bi = 0x7fffffff;
    for (int c = lane; c < K_CODES; c += 32) {
        if (ad[c] <= thr) {
            const float* crow = cbq + (size_t)c * C_DIM;
            float acc = 0.f;
            for (int k = 0; k < C_DIM; k++) acc = fmaf(rs[k], __ldg(crow + k), acc);
            float v = __fadd_rn(__fsub_rn(rn, 2.0f * acc), __ldg(cn + c));
            if (v < bm || (v == bm && c < bi)) { bm = v; bi = c; }
        }
    }
#pragma unroll
    for (int o = 16; o; o >>= 1) {
        float om = __shfl_xor_sync(0xffffffffu, bm, o);
        int oi = __shfl_xor_sync(0xffffffffu, bi, o);
        if (om < bm || (om == bm && oi < bi)) { bm = om; bi = oi; }
    }
    if (lane == 0) { g_idx[q * P_PTS + p] = bi; g_minv[p] = bm; }
}

// -------- histogram + commit sum --------
__global__ void hist_sum_kernel(int q) {
    __shared__ int h[K_CODES];
    __shared__ float ws[8];
    int tid = threadIdx.x;
    for (int i = tid; i < K_CODES; i += 256) h[i] = 0;
    __syncthreads();
    float s = 0.f;
    for (int i = blockIdx.x * 256 + tid; i < P_PTS; i += gridDim.x * 256) {
        atomicAdd(&h[g_idx[q * P_PTS + i]], 1);
        s += g_minv[i];
    }
    __syncthreads();
#pragma unroll
    for (int o = 16; o; o >>= 1) s += __shfl_xor_sync(0xffffffffu, s, o);
    if ((tid & 31) == 0) ws[tid >> 5] = s;
    __syncthreads();
    if (tid < 8) {
        float v = ws[tid];
#pragma unroll
        for (int o = 4; o; o >>= 1) v += __shfl_xor_sync(0xffu, v, o);
        if (tid == 0) atomicAdd(&g_commit_accum, (double)v);
    }
    for (int i = tid; i < K_CODES; i += 256) {
        int c = h[i];
        if (c) atomicAdd(&g_hist[i], c);
    }
}

__global__ void perp_commit_kernel() {
    __shared__ float red[K_CODES];
    int t = threadIdx.x;
    float cnt = (float)g_hist[t];
    float prob = cnt * (1.0f / 65536.0f);
    red[t] = prob * logf(prob + 1e-7f);
    __syncthreads();
    for (int o = 256; o; o >>= 1) {
        if (t < o) red[t] += red[t + o];
        __syncthreads();
    }
    if (t == 0) {
        g_perp_total += (double)expf(-red[0]);
        g_loss_total += g_commit_accum * (1.0 / ((double)P_PTS * (double)C_DIM));
        g_commit_accum = 0.0;
    }
    g_hist[t] = 0;
}

// -------- residual update (warp per point) + next rnorm + pack reinit --------
__global__ void update_kernel(const float* __restrict__ cb, int q) {
    int gw = (blockIdx.x * blockDim.x + threadIdx.x) >> 5;
    int lane = threadIdx.x & 31;
    if (gw >= P_PTS) return;
    int idx = g_idx[q * P_PTS + gw];
    const float4* crow = (const float4*)(cb + ((size_t)q * K_CODES + idx) * C_DIM);
    float4* rrow = (float4*)(g_resid + (size_t)gw * C_DIM);
    float nsq = 0.f;
#pragma unroll
    for (int k = 0; k < 4; k++) {
        int j = lane + 32 * k;
        float4 r = rrow[j];
        float4 c = __ldg(&crow[j]);
        r.x -= c.x; r.y -= c.y; r.z -= c.z; r.w -= c.w;
        rrow[j] = r;
        nsq = fmaf(r.x, r.x, fmaf(r.y, r.y, fmaf(r.z, r.z, fmaf(r.w, r.w, nsq))));
    }
#pragma unroll
    for (int o = 16; o; o >>= 1) nsq += __shfl_xor_sync(0xffffffffu, nsq, o);
    if (lane == 0) { g_rnorm[gw] = nsq; g_pack[gw] = ~0ull; }
}

// -------- finalize --------
__global__ void transpose_out_kernel(const float* __restrict__ x, float* __restrict__ out) {
    __shared__ float tile[32][33];
    int tx = threadIdx.x, ty = threadIdx.y;
    int n = blockIdx.z, c0 = blockIdx.y * 32, t0 = blockIdx.x * 32;
#pragma unroll
    for (int i = 0; i < 4; i++) {
        int t = t0 + ty + i * 8;
        tile[ty + i * 8][tx] = g_resid[((size_t)n * T_DIM + t) * C_DIM + c0 + tx];
    }
    __syncthreads();
#pragma unroll
    for (int i = 0; i < 4; i++) {
        int c = c0 + ty + i * 8;
        size_t gix = ((size_t)n * C_DIM + c) * T_DIM + t0 + tx;
        out[gix] = x[gix] - tile[tx][ty + i * 8];
    }
}

__global__ void finalize_idx_kernel(float* __restrict__ out) {
    for (int j = blockIdx.x * blockDim.x + threadIdx.x; j < IDX_ELEMS; j += gridDim.x * blockDim.x) {
        int p = j / Q_LAYERS;
        int q = j - p * Q_LAYERS;
        out[QUANT_ELEMS + j] = (float)g_idx[q * P_PTS + p];
    }
}

__global__ void finalize_scalar_kernel(float* __restrict__ out) {
    out[QUANT_ELEMS + IDX_ELEMS]     = (float)(g_loss_total * (1.0 / Q_LAYERS));
    out[QUANT_ELEMS + IDX_ELEMS + 1] = (float)(g_perp_total * (1.0 / Q_LAYERS));
}

extern "C" void kernel_launch(void* const* d_in, const int* in_sizes, int n_in,
                              void* d_out, int out_size) {
    const float* x  = (const float*)d_in[0];   // [32, 512, 2048]
    const float* cb = (const float*)d_in[1];   // [6, 512, 512]
    float* out = (float*)d_out;

    const int SMEM_ARG = 2 * 8192 * 4;   // 64 KB dynamic
    cudaFuncSetAttribute(argmin_tc_kernel, cudaFuncAttributeMaxDynamicSharedMemorySize, SMEM_ARG);

    init_kernel<<<1, 512>>>();
    transpose_in_kernel<<<dim3(64, 16, 32), dim3(32, 8)>>>(x);
    prep_kernel<<<8192, 256>>>();
    cbnorm_kernel<<<384, 256>>>(cb);

    for (int q = 0; q < Q_LAYERS; q++) {
        argmin_tc_kernel<<<dim3(512, 4), 256, SMEM_ARG>>>(cb, q);
        rescore_kernel<<<8192, 256>>>(cb, q);
        hist_sum_kernel<<<64, 256>>>(q);
        perp_commit_kernel<<<1, 512>>>();
        update_kernel<<<8192, 256>>>(cb, q);
    }

    transpose_out_kernel<<<dim3(64, 16, 32), dim3(32, 8)>>>(x, out);
    finalize_idx_kernel<<<384, 256>>>(out);
    finalize_scalar_kernel<<<1, 1>>>(out);
}

// round 9
// speedup vs baseline: 1.0989x; 1.0989x over previous
#include <cuda_runtime.h>
#include <cstdint>

// ResidualVQ eval forward — Round 8: int8 dp4a approx distance GEMM with
// rigorous per-(p,k) error bounds -> candidate set -> exact fp32 rescore
// (bit-identical to R1's argmin arithmetic; R7 verified this equivalence).

#define N_DIM 32
#define C_DIM 512
#define T_DIM 2048
#define K_CODES 512
#define Q_LAYERS 6
#define P_PTS (N_DIM * T_DIM)                 // 65536
#define QUANT_ELEMS (N_DIM * C_DIM * T_DIM)   // 33554432
#define IDX_ELEMS (P_PTS * Q_LAYERS)
#define CAND_MAX 64
#define EPS_BOUND 0.05f

// -------- device scratch --------
__device__ float    g_resid[(size_t)P_PTS * C_DIM];    // [p][c]
__device__ uint32_t g_qa[(size_t)P_PTS * 128];         // int8x4 packed residual
__device__ uint32_t g_qb[Q_LAYERS * K_CODES * 128];    // int8x4 packed codebook
__device__ float    g_sa[P_PTS], g_s1a[P_PTS], g_rnorm[P_PTS];
__device__ float    g_sb[Q_LAYERS * K_CODES], g_s1b[Q_LAYERS * K_CODES];
__device__ float    g_cbnorm[Q_LAYERS * K_CODES];      // exact (R1 arithmetic)
__device__ int      g_ccnt[P_PTS];
__device__ short    g_cand[(size_t)P_PTS * CAND_MAX];
__device__ float    g_minv[P_PTS];
__device__ int      g_idx[Q_LAYERS * P_PTS];
__device__ int      g_hist[K_CODES];
__device__ double   g_commit_accum, g_loss_total, g_perp_total;

// -------- helpers --------
__device__ __forceinline__ uint32_t pack4(float4 v, float inv) {
    int a = __float2int_rn(v.x * inv), b = __float2int_rn(v.y * inv);
    int c = __float2int_rn(v.z * inv), d = __float2int_rn(v.w * inv);
    return (a & 0xff) | ((b & 0xff) << 8) | ((c & 0xff) << 16) | ((d & 0xff) << 24);
}
// warp-wide quantize of one 512-float row held as float4 r[4] (j = lane+32k).
__device__ __forceinline__ void quant_row(const float4* r, int lane, int p,
                                          uint32_t* qa_row) {
    float amax = 0.f, s1 = 0.f, rn = 0.f;
#pragma unroll
    for (int k = 0; k < 4; k++) {
        float4 v = r[k];
        amax = fmaxf(amax, fmaxf(fmaxf(fabsf(v.x), fabsf(v.y)), fmaxf(fabsf(v.z), fabsf(v.w))));
        s1 += fabsf(v.x) + fabsf(v.y) + fabsf(v.z) + fabsf(v.w);
        rn = fmaf(v.x, v.x, fmaf(v.y, v.y, fmaf(v.z, v.z, fmaf(v.w, v.w, rn))));
    }
#pragma unroll
    for (int o = 16; o; o >>= 1) {
        amax = fmaxf(amax, __shfl_xor_sync(0xffffffffu, amax, o));
        s1 += __shfl_xor_sync(0xffffffffu, s1, o);
        rn += __shfl_xor_sync(0xffffffffu, rn, o);
    }
    amax = fmaxf(amax, 1e-30f);
    float inv = 127.0f / amax;
#pragma unroll
    for (int k = 0; k < 4; k++)
        qa_row[lane + 32 * k] = pack4(r[k], inv);
    if (lane == 0) {
        g_sa[p] = amax * (1.0f / 127.0f);
        g_s1a[p] = s1;
        g_rnorm[p] = rn;
        g_ccnt[p] = 0;
    }
}

// -------- init / layout --------
__global__ void init_kernel() {
    int t = threadIdx.x;
    if (t < K_CODES) g_hist[t] = 0;
    if (t == 0) { g_commit_accum = 0.0; g_loss_total = 0.0; g_perp_total = 0.0; }
}

// x[n][c][t] -> resid[n*T+t][c]
__global__ void transpose_in_kernel(const float* __restrict__ x) {
    __shared__ float tile[32][33];
    int tx = threadIdx.x, ty = threadIdx.y;
    int n = blockIdx.z, c0 = blockIdx.y * 32, t0 = blockIdx.x * 32;
#pragma unroll
    for (int i = 0; i < 4; i++) {
        int c = c0 + ty + i * 8;
        tile[ty + i * 8][tx] = x[((size_t)n * C_DIM + c) * T_DIM + t0 + tx];
    }
    __syncthreads();
#pragma unroll
    for (int i = 0; i < 4; i++) {
        int t = t0 + ty + i * 8;
        g_resid[((size_t)n * T_DIM + t) * C_DIM + c0 + tx] = tile[tx][ty + i * 8];
    }
}

// quantize layer-0 residual (warp per point)
__global__ void prep_kernel() {
    int gw = (blockIdx.x * blockDim.x + threadIdx.x) >> 5;
    int lane = threadIdx.x & 31;
    if (gw >= P_PTS) return;
    const float4* rrow = (const float4*)(g_resid + (size_t)gw * C_DIM);
    float4 r[4];
#pragma unroll
    for (int k = 0; k < 4; k++) r[k] = rrow[lane + 32 * k];
    quant_row(r, lane, gw, g_qa + (size_t)gw * 128);
}

// exact ||c||^2 (identical to R1's cbnorm)
__global__ void cbnorm_kernel(const float* __restrict__ cb) {
    int gw = (blockIdx.x * blockDim.x + threadIdx.x) >> 5;
    int lane = threadIdx.x & 31;
    if (gw >= Q_LAYERS * K_CODES) return;
    const float* row = cb + (size_t)gw * C_DIM;
    float s = 0.f;
    for (int c = lane; c < C_DIM; c += 32) { float v = row[c]; s = fmaf(v, v, s); }
#pragma unroll
    for (int o = 16; o; o >>= 1) s += __shfl_xor_sync(0xffffffffu, s, o);
    if (lane == 0) g_cbnorm[gw] = s;
}

// quantize codebook rows (warp per row, all layers)
__global__ void cbquant_kernel(const float* __restrict__ cb) {
    int gw = (blockIdx.x * blockDim.x + threadIdx.x) >> 5;
    int lane = threadIdx.x & 31;
    if (gw >= Q_LAYERS * K_CODES) return;
    const float4* row = (const float4*)(cb + (size_t)gw * C_DIM);
    float4 r[4];
    float amax = 0.f, s1 = 0.f;
#pragma unroll
    for (int k = 0; k < 4; k++) {
        r[k] = row[lane + 32 * k];
        float4 v = r[k];
        amax = fmaxf(amax, fmaxf(fmaxf(fabsf(v.x), fabsf(v.y)), fmaxf(fabsf(v.z), fabsf(v.w))));
        s1 += fabsf(v.x) + fabsf(v.y) + fabsf(v.z) + fabsf(v.w);
    }
#pragma unroll
    for (int o = 16; o; o >>= 1) {
        amax = fmaxf(amax, __shfl_xor_sync(0xffffffffu, amax, o));
        s1 += __shfl_xor_sync(0xffffffffu, s1, o);
    }
    amax = fmaxf(amax, 1e-30f);
    float inv = 127.0f / amax;
    uint32_t* qrow = g_qb + (size_t)gw * 128;
#pragma unroll
    for (int k = 0; k < 4; k++) qrow[lane + 32 * k] = pack4(r[k], inv);
    if (lane == 0) { g_sb[gw] = amax * (1.0f / 127.0f); g_s1b[gw] = s1; }
}

// -------- phase A: dp4a distance GEMM + rigorous candidate selection --------
// Block: 32 points x ALL 512 codes. 256 threads: tm=tid>>5 (8 pt-groups of 4),
// tn=tid&31 (codes tn+32j, j=0..15). K chunked at 32 bytes (8 u32 words).
__global__ __launch_bounds__(256, 2) void gemmq_kernel(int q) {
    __shared__ uint32_t sA[2][32 * 9];
    __shared__ uint32_t sB[2][512 * 9];
    __shared__ float s_sb[512], s_s1b[512], s_cn[512];
    __shared__ float s_sa[32], s_s1a[32], s_rn[32];

    const int tid = threadIdx.x;
    const int tm = tid >> 5, tn = tid & 31;
    const int p0 = blockIdx.x * 32;

    for (int i = tid; i < 512; i += 256) {
        s_sb[i] = g_sb[q * K_CODES + i];
        s_s1b[i] = g_s1b[q * K_CODES + i];
        s_cn[i] = g_cbnorm[q * K_CODES + i];
    }
    if (tid < 32) {
        s_sa[tid] = g_sa[p0 + tid];
        s_s1a[tid] = g_s1a[p0 + tid];
        s_rn[tid] = g_rnorm[p0 + tid];
    }

    // load coords
    const int ptL = tid >> 3, wL = tid & 7;         // A: 1 word/thread
    int acc[4][16];
#pragma unroll
    for (int i = 0; i < 4; i++)
#pragma unroll
        for (int j = 0; j < 16; j++) acc[i][j] = 0;

    // stage chunk 0
    sA[0][ptL * 9 + wL] = g_qa[(size_t)(p0 + ptL) * 128 + wL];
#pragma unroll
    for (int i = 0; i < 16; i++) {
        int lin = tid + i * 256;
        int code = lin >> 3, w = lin & 7;
        sB[0][code * 9 + w] = g_qb[((size_t)q * K_CODES + code) * 128 + w];
    }
    __syncthreads();

    for (int ch = 0; ch < 16; ch++) {
        const int buf = ch & 1;
        uint32_t pA = 0, pB[16];
        if (ch < 15) {
            pA = g_qa[(size_t)(p0 + ptL) * 128 + (ch + 1) * 8 + wL];
#pragma unroll
            for (int i = 0; i < 16; i++) {
                int lin = tid + i * 256;
                int code = lin >> 3, w = lin & 7;
                pB[i] = g_qb[((size_t)q * K_CODES + code) * 128 + (ch + 1) * 8 + w];
            }
        }
#pragma unroll
        for (int w = 0; w < 8; w++) {
            uint32_t a0 = sA[buf][(tm * 4 + 0) * 9 + w];
            uint32_t a1 = sA[buf][(tm * 4 + 1) * 9 + w];
            uint32_t a2 = sA[buf][(tm * 4 + 2) * 9 + w];
            uint32_t a3 = sA[buf][(tm * 4 + 3) * 9 + w];
#pragma unroll
            for (int j = 0; j < 16; j++) {
                uint32_t b = sB[buf][(tn + 32 * j) * 9 + w];
                acc[0][j] = __dp4a((int)a0, (int)b, acc[0][j]);
                acc[1][j] = __dp4a((int)a1, (int)b, acc[1][j]);
                acc[2][j] = __dp4a((int)a2, (int)b, acc[2][j]);
                acc[3][j] = __dp4a((int)a3, (int)b, acc[3][j]);
            }
        }
        if (ch < 15) {
            const int nb = buf ^ 1;
            sA[nb][ptL * 9 + wL] = pA;
#pragma unroll
            for (int i = 0; i < 16; i++) {
                int lin = tid + i * 256;
                int code = lin >> 3, w = lin & 7;
                sB[nb][code * 9 + w] = pB[i];
            }
        }
        __syncthreads();
    }

    // epilogue: bounds, per-point U (min of upper bounds), candidate list.
#pragma unroll
    for (int i = 0; i < 4; i++) {
        const int pt = p0 + tm * 4 + i;
        const float sa = s_sa[tm * 4 + i], s1a = s_s1a[tm * 4 + i], rn = s_rn[tm * 4 + i];
        float um = 3.4e38f;
#pragma unroll
        for (int j = 0; j < 16; j++) {
            int k = tn + 32 * j;
            float ss = sa * s_sb[k];
            float v = __fadd_rn(__fsub_rn(rn, 2.0f * ss * (float)acc[i][j]), s_cn[k]);
            float e = fmaf(s_sb[k], s1a, fmaf(sa, s_s1b[k], 256.0f * ss)) + EPS_BOUND;
            um = fminf(um, v + e);
        }
#pragma unroll
        for (int o = 16; o; o >>= 1) um = fminf(um, __shfl_xor_sync(0xffffffffu, um, o));
#pragma unroll
        for (int j = 0; j < 16; j++) {
            int k = tn + 32 * j;
            float ss = sa * s_sb[k];
            float v = __fadd_rn(__fsub_rn(rn, 2.0f * ss * (float)acc[i][j]), s_cn[k]);
            float e = fmaf(s_sb[k], s1a, fmaf(sa, s_s1b[k], 256.0f * ss)) + EPS_BOUND;
            if (v - e <= um) {
                int pos = atomicAdd(&g_ccnt[pt], 1);
                if (pos < CAND_MAX) g_cand[(size_t)pt * CAND_MAX + pos] = (short)k;
            }
        }
    }
}

// -------- phase B: exact rescore of candidates (R1-identical arithmetic) --------
__global__ __launch_bounds__(256) void rescore_kernel(const float* __restrict__ cb, int q) {
    __shared__ float rsm[8][512];
    const int w = threadIdx.x >> 5, lane = threadIdx.x & 31;
    const int p = blockIdx.x * 8 + w;

    const float4* rrow = (const float4*)(g_resid + (size_t)p * C_DIM);
    float4* rs4 = (float4*)rsm[w];
#pragma unroll
    for (int i = 0; i < 4; i++) rs4[lane + 32 * i] = rrow[lane + 32 * i];
    __syncwarp();

    // exact ||r||^2, c ascending (matches R1)
    float rn = 0.f;
    const float4* rf4 = (const float4*)rsm[w];
    for (int i = 0; i < 128; i++) {
        float4 v = rf4[i];
        rn = fmaf(v.x, v.x, rn); rn = fmaf(v.y, v.y, rn);
        rn = fmaf(v.z, v.z, rn); rn = fmaf(v.w, v.w, rn);
    }

    const float* cbq = cb + (size_t)q * K_CODES * C_DIM;
    const float* cn = g_cbnorm + q * K_CODES;
    const int cnt = g_ccnt[p];
    float bm = 3.4e38f; int bi = 0x7fffffff;

    if (cnt <= CAND_MAX) {
        for (int ci = lane; ci < cnt; ci += 32) {
            int c = g_cand[(size_t)p * CAND_MAX + ci];
            const float4* crow = (const float4*)(cbq + (size_t)c * C_DIM);
            float acc = 0.f;
            for (int i = 0; i < 128; i++) {
                float4 cv = __ldg(crow + i);
                float4 rv = rf4[i];
                acc = fmaf(rv.x, cv.x, acc); acc = fmaf(rv.y, cv.y, acc);
                acc = fmaf(rv.z, cv.z, acc); acc = fmaf(rv.w, cv.w, acc);
            }
            float v = __fadd_rn(__fsub_rn(rn, 2.0f * acc), __ldg(cn + c));
            if (v < bm || (v == bm && c < bi)) { bm = v; bi = c; }
        }
    } else {
        for (int c = lane; c < K_CODES; c += 32) {
            const float4* crow = (const float4*)(cbq + (size_t)c * C_DIM);
            float acc = 0.f;
            for (int i = 0; i < 128; i++) {
                float4 cv = __ldg(crow + i);
                float4 rv = rf4[i];
                acc = fmaf(rv.x, cv.x, acc); acc = fmaf(rv.y, cv.y, acc);
                acc = fmaf(rv.z, cv.z, acc); acc = fmaf(rv.w, cv.w, acc);
            }
            float v = __fadd_rn(__fsub_rn(rn, 2.0f * acc), __ldg(cn + c));
            if (v < bm || (v == bm && c < bi)) { bm = v; bi = c; }
        }
    }
#pragma unroll
    for (int o = 16; o; o >>= 1) {
        float om = __shfl_xor_sync(0xffffffffu, bm, o);
        int oi = __shfl_xor_sync(0xffffffffu, bi, o);
        if (om < bm || (om == bm && oi < bi)) { bm = om; bi = oi; }
    }
    if (lane == 0) { g_idx[q * P_PTS + p] = bi; g_minv[p] = bm; }
}

// -------- histogram + commit sum --------
__global__ void hist_sum_kernel(int q) {
    __shared__ int h[K_CODES];
    __shared__ float ws[8];
    int tid = threadIdx.x;
    for (int i = tid; i < K_CODES; i += 256) h[i] = 0;
    __syncthreads();
    float s = 0.f;
    for (int i = blockIdx.x * 256 + tid; i < P_PTS; i += gridDim.x * 256) {
        atomicAdd(&h[g_idx[q * P_PTS + i]], 1);
        s += g_minv[i];
    }
    __syncthreads();
#pragma unroll
    for (int o = 16; o; o >>= 1) s += __shfl_xor_sync(0xffffffffu, s, o);
    if ((tid & 31) == 0) ws[tid >> 5] = s;
    __syncthreads();
    if (tid < 8) {
        float v = ws[tid];
#pragma unroll
        for (int o = 4; o; o >>= 1) v += __shfl_xor_sync(0xffu, v, o);
        if (tid == 0) atomicAdd(&g_commit_accum, (double)v);
    }
    for (int i = tid; i < K_CODES; i += 256) {
        int c = h[i];
        if (c) atomicAdd(&g_hist[i], c);
    }
}

__global__ void perp_commit_kernel() {
    __shared__ float red[K_CODES];
    int t = threadIdx.x;
    float cnt = (float)g_hist[t];
    float prob = cnt * (1.0f / 65536.0f);
    red[t] = prob * logf(prob + 1e-7f);
    __syncthreads();
    for (int o = 256; o; o >>= 1) {
        if (t < o) red[t] += red[t + o];
        __syncthreads();
    }
    if (t == 0) {
        g_perp_total += (double)expf(-red[0]);
        g_loss_total += g_commit_accum * (1.0 / ((double)P_PTS * (double)C_DIM));
        g_commit_accum = 0.0;
    }
    g_hist[t] = 0;
}

// -------- residual update (warp per point) + quantize for next layer --------
__global__ void update_kernel(const float* __restrict__ cb, int q) {
    int gw = (blockIdx.x * blockDim.x + threadIdx.x) >> 5;
    int lane = threadIdx.x & 31;
    if (gw >= P_PTS) return;
    int idx = g_idx[q * P_PTS + gw];
    const float4* crow = (const float4*)(cb + ((size_t)q * K_CODES + idx) * C_DIM);
    float4* rrow = (float4*)(g_resid + (size_t)gw * C_DIM);
    float4 r[4];
#pragma unroll
    for (int k = 0; k < 4; k++) {
        int j = lane + 32 * k;
        float4 rv = rrow[j];
        float4 cv = __ldg(&crow[j]);
        rv.x -= cv.x; rv.y -= cv.y; rv.z -= cv.z; rv.w -= cv.w;
        rrow[j] = rv;
        r[k] = rv;
    }
    quant_row(r, lane, gw, g_qa + (size_t)gw * 128);
}

// -------- finalize --------
__global__ void transpose_out_kernel(const float* __restrict__ x, float* __restrict__ out) {
    __shared__ float tile[32][33];
    int tx = threadIdx.x, ty = threadIdx.y;
    int n = blockIdx.z, c0 = blockIdx.y * 32, t0 = blockIdx.x * 32;
#pragma unroll
    for (int i = 0; i < 4; i++) {
        int t = t0 + ty + i * 8;
        tile[ty + i * 8][tx] = g_resid[((size_t)n * T_DIM + t) * C_DIM + c0 + tx];
    }
    __syncthreads();
#pragma unroll
    for (int i = 0; i < 4; i++) {
        int c = c0 + ty + i * 8;
        size_t gix = ((size_t)n * C_DIM + c) * T_DIM + t0 + tx;
        out[gix] = x[gix] - tile[tx][ty + i * 8];
    }
}

__global__ void finalize_idx_kernel(float* __restrict__ out) {
    for (int j = blockIdx.x * blockDim.x + threadIdx.x; j < IDX_ELEMS; j += gridDim.x * blockDim.x) {
        int p = j / Q_LAYERS;
        int q = j - p * Q_LAYERS;
        out[QUANT_ELEMS + j] = (float)g_idx[q * P_PTS + p];
    }
}

__global__ void finalize_scalar_kernel(float* __restrict__ out) {
    out[QUANT_ELEMS + IDX_ELEMS]     = (float)(g_loss_total * (1.0 / Q_LAYERS));
    out[QUANT_ELEMS + IDX_ELEMS + 1] = (float)(g_perp_total * (1.0 / Q_LAYERS));
}

extern "C" void kernel_launch(void* const* d_in, const int* in_sizes, int n_in,
                              void* d_out, int out_size) {
    const float* x  = (const float*)d_in[0];   // [32, 512, 2048]
    const float* cb = (const float*)d_in[1];   // [6, 512, 512]
    float* out = (float*)d_out;

    init_kernel<<<1, 512>>>();
    transpose_in_kernel<<<dim3(64, 16, 32), dim3(32, 8)>>>(x);
    prep_kernel<<<8192, 256>>>();
    cbnorm_kernel<<<384, 256>>>(cb);
    cbquant_kernel<<<384, 256>>>(cb);

    for (int q = 0; q < Q_LAYERS; q++) {
        gemmq_kernel<<<P_PTS / 32, 256>>>(q);
        rescore_kernel<<<8192, 256>>>(cb, q);
        hist_sum_kernel<<<64, 256>>>(q);
        perp_commit_kernel<<<1, 512>>>();
        update_kernel<<<8192, 256>>>(cb, q);
    }

    transpose_out_kernel<<<dim3(64, 16, 32), dim3(32, 8)>>>(x, out);
    finalize_idx_kernel<<<384, 256>>>(out);
    finalize_scalar_kernel<<<1, 1>>>(out);
}